// round 1
// baseline (speedup 1.0000x reference)
#include <cuda_runtime.h>
#include <cstdint>

#define BB 32
#define CC 256
#define HH 56
#define WW 56
#define OH 28
#define OW 28
#define C2 512

// ---- scratch (static device arrays; no allocation) ----
__device__ unsigned d_xbits[BB * HH * WW * 8];     // sign bits of x, [b][h][w][8 words]
__device__ unsigned d_w3bits[CC * 9 * 8];          // [oc][tap][8 words]
__device__ unsigned d_w1bits[C2 * 8];              // [oc2][8 words]
__device__ float    d_pool [BB * OH * OW * CC];    // avgpool2x2(x), [b][oh][ow][c]
__device__ float    d_hval [BB * OH * OW * CC];    // h, [b][oh][ow][c]
__device__ unsigned d_hbits[BB * OH * OW * 8];     // sign bits of h, [b][oh][ow][8 words]

// ---------------- pack weights ----------------
__global__ void pack_w3_kernel(const float* __restrict__ w3) {
    int idx = blockIdx.x * blockDim.x + threadIdx.x;   // oc*72 + tap*8 + word
    if (idx >= CC * 9 * 8) return;
    int word = idx & 7;
    int tap  = (idx >> 3) % 9;
    int oc   = idx / 72;
    unsigned bits = 0;
#pragma unroll
    for (int j = 0; j < 32; j++) {
        float v = w3[((size_t)(oc * CC + word * 32 + j)) * 9 + tap]; // OIHW
        bits |= (v < 0.f ? 1u : 0u) << j;
    }
    d_w3bits[idx] = bits;
}

__global__ void pack_w1_kernel(const float* __restrict__ w1) {
    int idx = blockIdx.x * blockDim.x + threadIdx.x;   // oc2*8 + word
    if (idx >= C2 * 8) return;
    int word = idx & 7;
    int oc   = idx >> 3;
    unsigned bits = 0;
#pragma unroll
    for (int j = 0; j < 32; j++) {
        float v = w1[(size_t)oc * CC + word * 32 + j];
        bits |= (v < 0.f ? 1u : 0u) << j;
    }
    d_w1bits[idx] = bits;
}

// ---------------- pack x sign bits ----------------
// block = b*112 + h*2 + cg (cg selects 128-channel half); 128 threads
__global__ void pack_x_kernel(const float* __restrict__ x) {
    int blk = blockIdx.x;
    int cg  = blk & 1;
    int h   = (blk >> 1) % HH;
    int b   = blk / (HH * 2);
    __shared__ float xs[128][57];   // stride 57 (odd) -> conflict-free column reads
    int tid = threadIdx.x;
    const float* xp = x + ((size_t)(b * CC + cg * 128) * HH + h) * WW;
    for (int i = tid; i < 128 * WW; i += 128) {
        int c = i / WW, w = i % WW;
        xs[c][w] = xp[(size_t)c * HH * WW + w];
    }
    __syncthreads();
    int g = tid >> 5, lane = tid & 31;
    unsigned* ob = d_xbits + ((size_t)(b * HH + h) * WW) * 8 + cg * 4 + g;
    for (int w = 0; w < WW; w++) {
        unsigned m = __ballot_sync(0xffffffffu, xs[g * 32 + lane][w] < 0.f);
        if (lane == 0) ob[(size_t)w * 8] = m;
    }
}

// ---------------- avgpool 2x2 -> [b][oh][ow][c] ----------------
__global__ void pool_kernel(const float* __restrict__ x) {
    int idx = blockIdx.x * blockDim.x + threadIdx.x;
    if (idx >= BB * CC * OH * OW) return;
    int ow = idx % OW;
    int oh = (idx / OW) % OH;
    int c  = (idx / (OW * OH)) % CC;
    int b  = idx / (OW * OH * CC);
    const float* p = x + (((size_t)(b * CC + c)) * HH + 2 * oh) * WW + 2 * ow;
    float s = p[0] + p[1] + p[WW] + p[WW + 1];
    d_pool[(((size_t)(b * OH + oh)) * OW + ow) * CC + c] = 0.25f * s;
}

// ---------------- conv3x3 stride2 (XNOR-popcount) + BN + pool add + re-binarize ----------------
// block = b*28 + oh ; 256 threads, thread = oc
__global__ __launch_bounds__(256, 2) void conv3_kernel(
    const float* __restrict__ g3, const float* __restrict__ b3,
    const float* __restrict__ m3, const float* __restrict__ v3) {
    int oh = blockIdx.x % OH;
    int b  = blockIdx.x / OH;
    int oc = threadIdx.x;
    __shared__ __align__(16) unsigned xs[3][WW][8];

    // stage 3 input rows (ih = 2*oh-1 .. 2*oh+1); row -1 skipped (only at oh==0)
    {
        int ih0 = 2 * oh - 1;
        for (int i = threadIdx.x; i < 3 * WW * 2; i += 256) {  // 336 uint4
            int r = i / (WW * 2);
            int j = i % (WW * 2);
            int ih = ih0 + r;
            if (ih >= 0) {
                const uint4* src = (const uint4*)(d_xbits + ((size_t)(b * HH + ih) * WW) * 8);
                ((uint4*)&xs[r][0][0])[j] = src[j];
            }
        }
    }

    // weights for this oc: 72 words resident in registers
    unsigned wreg[72];
    {
        const uint4* wp = (const uint4*)(d_w3bits + (size_t)oc * 72);
#pragma unroll
        for (int i = 0; i < 18; i++) {
            uint4 t = wp[i];
            wreg[i * 4 + 0] = t.x; wreg[i * 4 + 1] = t.y;
            wreg[i * 4 + 2] = t.z; wreg[i * 4 + 3] = t.w;
        }
    }
    float inv  = g3[oc] * rsqrtf(v3[oc] + 1e-5f);
    float bias = b3[oc] - m3[oc] * inv;
    __syncthreads();

    int lane = oc & 31, wid = oc >> 5;
    const float* poolrow = d_pool + ((size_t)(b * OH + oh)) * OW * CC;
    float*       hrow    = d_hval + ((size_t)(b * OH + oh)) * OW * CC;
    unsigned*    hbrow   = d_hbits + ((size_t)(b * OH + oh)) * OW * 8;
    int khmin = (oh == 0) ? 1 : 0;
    int nrows = 3 - khmin;

    for (int ow = 0; ow < OW; ow++) {
        int iw = 2 * ow - 1;
        int s0 = 0, s1 = 0, s2 = 0, s3 = 0;
#pragma unroll
        for (int kh = 0; kh < 3; kh++) {
            if (kh < khmin) continue;               // uniform branch
#pragma unroll
            for (int kw = 0; kw < 3; kw++) {
                int col = iw + kw;
                if (col < 0) continue;              // only kw==0 at ow==0
                const uint4* xp = (const uint4*)&xs[kh][col][0];
                uint4 a0 = xp[0], a1 = xp[1];
                const unsigned* w = &wreg[(kh * 3 + kw) * 8];
                s0 += __popc(a0.x ^ w[0]) + __popc(a0.y ^ w[1]);
                s1 += __popc(a0.z ^ w[2]) + __popc(a0.w ^ w[3]);
                s2 += __popc(a1.x ^ w[4]) + __popc(a1.y ^ w[5]);
                s3 += __popc(a1.z ^ w[6]) + __popc(a1.w ^ w[7]);
            }
        }
        int ncols = (ow == 0) ? 2 : 3;
        int s = (s0 + s1) + (s2 + s3);
        float dot = (float)(nrows * ncols * CC - 2 * s);
        float h = fmaf(dot, inv, bias) + poolrow[(size_t)ow * CC + oc];
        hrow[(size_t)ow * CC + oc] = h;
        unsigned m = __ballot_sync(0xffffffffu, h < 0.f);
        if (lane == 0) hbrow[ow * 8 + wid] = m;
    }
}

// ---------------- conv1x1 (XNOR-popcount) + BN + concat shortcut -> out (NCHW) ----------------
// block = b*28 + oh ; 512 threads, thread = oc2
__global__ __launch_bounds__(512, 2) void conv1_kernel(
    const float* __restrict__ g1, const float* __restrict__ b1,
    const float* __restrict__ m1, const float* __restrict__ v1,
    float* __restrict__ out) {
    int oh = blockIdx.x % OH;
    int b  = blockIdx.x / OH;
    int oc = threadIdx.x;
    __shared__ __align__(16) unsigned hb[OW][8];
    for (int i = threadIdx.x; i < OW * 8; i += 512) {
        ((unsigned*)hb)[i] = d_hbits[((size_t)(b * OH + oh)) * OW * 8 + i];
    }
    unsigned w[8];
    {
        const uint4* wp = (const uint4*)(d_w1bits + (size_t)oc * 8);
        uint4 t0 = wp[0], t1 = wp[1];
        w[0] = t0.x; w[1] = t0.y; w[2] = t0.z; w[3] = t0.w;
        w[4] = t1.x; w[5] = t1.y; w[6] = t1.z; w[7] = t1.w;
    }
    float inv  = g1[oc] * rsqrtf(v1[oc] + 1e-5f);
    float bias = b1[oc] - m1[oc] * inv;
    __syncthreads();

    const float* hrow = d_hval + ((size_t)(b * OH + oh)) * OW * CC;
    float* orow = out + (((size_t)(b * C2 + oc)) * OH + oh) * OW;
    int hc = oc & (CC - 1);
    for (int ow = 0; ow < OW; ow++) {
        const uint4* xp = (const uint4*)&hb[ow][0];
        uint4 a0 = xp[0], a1 = xp[1];
        int s = __popc(a0.x ^ w[0]) + __popc(a0.y ^ w[1])
              + __popc(a0.z ^ w[2]) + __popc(a0.w ^ w[3])
              + __popc(a1.x ^ w[4]) + __popc(a1.y ^ w[5])
              + __popc(a1.z ^ w[6]) + __popc(a1.w ^ w[7]);
        float dot = (float)(CC - 2 * s);
        orow[ow] = fmaf(dot, inv, bias) + hrow[(size_t)ow * CC + hc];
    }
}

extern "C" void kernel_launch(void* const* d_in, const int* in_sizes, int n_in,
                              void* d_out, int out_size) {
    const float* x  = (const float*)d_in[0];
    const float* w3 = (const float*)d_in[1];
    const float* g3 = (const float*)d_in[2];
    const float* b3 = (const float*)d_in[3];
    const float* m3 = (const float*)d_in[4];
    const float* v3 = (const float*)d_in[5];
    const float* w1 = (const float*)d_in[6];
    const float* g1 = (const float*)d_in[7];
    const float* b1 = (const float*)d_in[8];
    const float* m1 = (const float*)d_in[9];
    const float* v1 = (const float*)d_in[10];
    float* out = (float*)d_out;
    (void)in_sizes; (void)n_in; (void)out_size;

    pack_w3_kernel<<<(CC * 9 * 8 + 255) / 256, 256>>>(w3);
    pack_w1_kernel<<<(C2 * 8 + 255) / 256, 256>>>(w1);
    pack_x_kernel<<<BB * HH * 2, 128>>>(x);
    pool_kernel<<<(BB * CC * OH * OW + 255) / 256, 256>>>(x);
    conv3_kernel<<<BB * OH, 256>>>(g3, b3, m3, v3);
    conv1_kernel<<<BB * OH, 512>>>(g1, b1, m1, v1, out);
}

// round 3
// speedup vs baseline: 1.7489x; 1.7489x over previous
#include <cuda_runtime.h>
#include <cstdint>

#define BB 32
#define CC 256
#define HH 56
#define WW 56
#define OH 28
#define OW 28
#define C2 512

// ---- scratch (static device arrays; no allocation) ----
__device__ unsigned d_w3bits[CC * 9 * 8];          // [oc][tap][8 words]
__device__ unsigned d_w1bits[C2 * 8];              // [oc2][8 words]

// ---------------- pack weights ----------------
__global__ void pack_w3_kernel(const float* __restrict__ w3) {
    int idx = blockIdx.x * blockDim.x + threadIdx.x;   // oc*72 + tap*8 + word
    if (idx >= CC * 9 * 8) return;
    int word = idx & 7;
    int tap  = (idx >> 3) % 9;
    int oc   = idx / 72;
    unsigned bits = 0;
#pragma unroll
    for (int j = 0; j < 32; j++) {
        float v = w3[((size_t)(oc * CC + word * 32 + j)) * 9 + tap]; // OIHW
        bits |= (v < 0.f ? 1u : 0u) << j;
    }
    d_w3bits[idx] = bits;
}

__global__ void pack_w1_kernel(const float* __restrict__ w1) {
    int idx = blockIdx.x * blockDim.x + threadIdx.x;   // oc2*8 + word
    if (idx >= C2 * 8) return;
    int word = idx & 7;
    int oc   = idx >> 3;
    unsigned bits = 0;
#pragma unroll
    for (int j = 0; j < 32; j++) {
        float v = w1[(size_t)oc * CC + word * 32 + j];
        bits |= (v < 0.f ? 1u : 0u) << j;
    }
    d_w1bits[idx] = bits;
}

// ================ fused megakernel ================
// block = b*28 + oh ; 256 threads, thread = channel (conv3 oc / conv1 input c)
// Phase 1: read 3 raw x rows, binarize via ballot -> smem bits, avgpool -> smem
// Phase 2: conv3x3 XNOR-popcount + BN + pool add -> h in smem (+ sign bits)
// Phase 3: conv1x1 XNOR-popcount + BN + concat shortcut -> out (NCHW, float4)
__global__ __launch_bounds__(256, 2) void fused_kernel(
    const float* __restrict__ x,
    const float* __restrict__ g3, const float* __restrict__ b3,
    const float* __restrict__ m3, const float* __restrict__ v3,
    const float* __restrict__ g1, const float* __restrict__ b1,
    const float* __restrict__ m1, const float* __restrict__ v1,
    float* __restrict__ out) {
    int oh = blockIdx.x % OH;
    int b  = blockIdx.x / OH;
    int oc = threadIdx.x;
    int lane = oc & 31, wid = oc >> 5;

    __shared__ __align__(16) unsigned xs[3][WW][8];   // sign bits of 3 input rows
    __shared__ float    hs[OW][CC];                   // pooled, then h
    __shared__ __align__(16) unsigned hb[OW][8];      // sign bits of h

    // ---- Phase 1: binarize + pool ----
    {
        float acc[OW];
#pragma unroll
        for (int r = 0; r < 3; r++) {
            int ih = 2 * oh - 1 + r;
            if (ih >= 0) {                             // uniform across block
                const float4* xp = (const float4*)(x + ((size_t)(b * CC + oc) * HH + ih) * WW);
                float4 v[14];
#pragma unroll
                for (int i = 0; i < 14; i++) v[i] = xp[i];
                const float* vf = (const float*)v;
                unsigned* xrow = &xs[r][0][wid];
#pragma unroll
                for (int col = 0; col < WW; col++) {
                    unsigned m = __ballot_sync(0xffffffffu, vf[col] < 0.f);
                    if (lane == 0) xrow[col * 8] = m;
                }
                if (r == 1) {
#pragma unroll
                    for (int ow = 0; ow < OW; ow++) acc[ow] = vf[2 * ow] + vf[2 * ow + 1];
                } else if (r == 2) {
#pragma unroll
                    for (int ow = 0; ow < OW; ow++) acc[ow] += vf[2 * ow] + vf[2 * ow + 1];
                }
            }
        }
#pragma unroll
        for (int ow = 0; ow < OW; ow++) hs[ow][oc] = 0.25f * acc[ow];
    }
    __syncthreads();

    // ---- Phase 2: conv3x3 popcount + BN + pool add + re-binarize ----
    {
        unsigned wreg[72];
        const uint4* wp = (const uint4*)(d_w3bits + (size_t)oc * 72);
#pragma unroll
        for (int i = 0; i < 18; i++) {
            uint4 t = wp[i];
            wreg[i * 4 + 0] = t.x; wreg[i * 4 + 1] = t.y;
            wreg[i * 4 + 2] = t.z; wreg[i * 4 + 3] = t.w;
        }
        float inv  = g3[oc] * rsqrtf(v3[oc] + 1e-5f);
        float bias = b3[oc] - m3[oc] * inv;
        int khmin = (oh == 0) ? 1 : 0;
        int nrows = 3 - khmin;

        for (int ow = 0; ow < OW; ow++) {
            int iw = 2 * ow - 1;
            int s0 = 0, s1 = 0, s2 = 0, s3 = 0;
#pragma unroll
            for (int kh = 0; kh < 3; kh++) {
                if (kh < khmin) continue;               // uniform
#pragma unroll
                for (int kw = 0; kw < 3; kw++) {
                    int col = iw + kw;
                    if (col < 0) continue;              // only kw==0 at ow==0
                    const uint4* xp2 = (const uint4*)&xs[kh][col][0];
                    uint4 a0 = xp2[0], a1 = xp2[1];
                    const unsigned* w = &wreg[(kh * 3 + kw) * 8];
                    s0 += __popc(a0.x ^ w[0]) + __popc(a0.y ^ w[1]);
                    s1 += __popc(a0.z ^ w[2]) + __popc(a0.w ^ w[3]);
                    s2 += __popc(a1.x ^ w[4]) + __popc(a1.y ^ w[5]);
                    s3 += __popc(a1.z ^ w[6]) + __popc(a1.w ^ w[7]);
                }
            }
            int ncols = (ow == 0) ? 2 : 3;
            int s = (s0 + s1) + (s2 + s3);
            float dot = (float)(nrows * ncols * CC - 2 * s);
            float h = fmaf(dot, inv, bias) + hs[ow][oc];
            hs[ow][oc] = h;
            unsigned m = __ballot_sync(0xffffffffu, h < 0.f);
            if (lane == 0) hb[ow][wid] = m;
        }
    }
    __syncthreads();

    // ---- Phase 3: conv1x1 popcount + BN + concat shortcut -> out ----
    {
        unsigned wa[8], wb[8];
        {
            const uint4* wpa = (const uint4*)(d_w1bits + (size_t)oc * 8);
            uint4 t0 = wpa[0], t1 = wpa[1];
            wa[0] = t0.x; wa[1] = t0.y; wa[2] = t0.z; wa[3] = t0.w;
            wa[4] = t1.x; wa[5] = t1.y; wa[6] = t1.z; wa[7] = t1.w;
            const uint4* wpb = (const uint4*)(d_w1bits + (size_t)(oc + CC) * 8);
            uint4 u0 = wpb[0], u1 = wpb[1];
            wb[0] = u0.x; wb[1] = u0.y; wb[2] = u0.z; wb[3] = u0.w;
            wb[4] = u1.x; wb[5] = u1.y; wb[6] = u1.z; wb[7] = u1.w;
        }
        float inva  = g1[oc] * rsqrtf(v1[oc] + 1e-5f);
        float biasa = b1[oc] - m1[oc] * inva;
        float invb  = g1[oc + CC] * rsqrtf(v1[oc + CC] + 1e-5f);
        float biasb = b1[oc + CC] - m1[oc + CC] * invb;

        float* orowa = out + (((size_t)(b * C2 + oc)) * OH + oh) * OW;
        float* orowb = orowa + (size_t)CC * OH * OW;

#pragma unroll
        for (int ow4 = 0; ow4 < OW; ow4 += 4) {
            float4 oa, ob;
            float* pa = (float*)&oa;
            float* pb = (float*)&ob;
#pragma unroll
            for (int k = 0; k < 4; k++) {
                int ow = ow4 + k;
                const uint4* xp3 = (const uint4*)&hb[ow][0];
                uint4 a0 = xp3[0], a1 = xp3[1];
                int sa = __popc(a0.x ^ wa[0]) + __popc(a0.y ^ wa[1])
                       + __popc(a0.z ^ wa[2]) + __popc(a0.w ^ wa[3])
                       + __popc(a1.x ^ wa[4]) + __popc(a1.y ^ wa[5])
                       + __popc(a1.z ^ wa[6]) + __popc(a1.w ^ wa[7]);
                int sb = __popc(a0.x ^ wb[0]) + __popc(a0.y ^ wb[1])
                       + __popc(a0.z ^ wb[2]) + __popc(a0.w ^ wb[3])
                       + __popc(a1.x ^ wb[4]) + __popc(a1.y ^ wb[5])
                       + __popc(a1.z ^ wb[6]) + __popc(a1.w ^ wb[7]);
                float hshort = hs[ow][oc];
                pa[k] = fmaf((float)(CC - 2 * sa), inva, biasa) + hshort;
                pb[k] = fmaf((float)(CC - 2 * sb), invb, biasb) + hshort;
            }
            *(float4*)(orowa + ow4) = oa;
            *(float4*)(orowb + ow4) = ob;
        }
    }
}

extern "C" void kernel_launch(void* const* d_in, const int* in_sizes, int n_in,
                              void* d_out, int out_size) {
    const float* x  = (const float*)d_in[0];
    const float* w3 = (const float*)d_in[1];
    const float* g3 = (const float*)d_in[2];
    const float* b3 = (const float*)d_in[3];
    const float* m3 = (const float*)d_in[4];
    const float* v3 = (const float*)d_in[5];
    const float* w1 = (const float*)d_in[6];
    const float* g1 = (const float*)d_in[7];
    const float* b1 = (const float*)d_in[8];
    const float* m1 = (const float*)d_in[9];
    const float* v1 = (const float*)d_in[10];
    float* out = (float*)d_out;
    (void)in_sizes; (void)n_in; (void)out_size;

    pack_w3_kernel<<<(CC * 9 * 8 + 255) / 256, 256>>>(w3);
    pack_w1_kernel<<<(C2 * 8 + 255) / 256, 256>>>(w1);
    fused_kernel<<<BB * OH, 256>>>(x, g3, b3, m3, v3, g1, b1, m1, v1, out);
}

// round 4
// speedup vs baseline: 1.7942x; 1.0259x over previous
#include <cuda_runtime.h>
#include <cstdint>

#define BB 32
#define CC 256
#define HH 56
#define WW 56
#define OH 28
#define OW 28
#define C2 512

// ---- scratch (static device arrays; no allocation) ----
__device__ unsigned d_w3bits[CC * 9 * 8];          // [oc][tap][8 words]
__device__ unsigned d_w1bits[C2 * 8];              // [oc2][8 words]

// extract even bits of x into low 16 bits
__device__ __forceinline__ unsigned cmpr_even(unsigned x) {
    x &= 0x55555555u;
    x = (x | (x >> 1)) & 0x33333333u;
    x = (x | (x >> 2)) & 0x0F0F0F0Fu;
    x = (x | (x >> 4)) & 0x00FF00FFu;
    x = (x | (x >> 8)) & 0x0000FFFFu;
    return x;
}

// ---------------- pack weights: warp per output word, lane = channel ----------------
__global__ void pack_w3_kernel(const float* __restrict__ w3) {
    int g = blockIdx.x * 8 + (threadIdx.x >> 5);   // linear word id = oc*72 + tap*8 + word
    int lane = threadIdx.x & 31;
    if (g >= CC * 9 * 8) return;
    int word = g & 7;
    int tap  = (g >> 3) % 9;
    int oc   = g / 72;
    float v = w3[((size_t)(oc * CC + word * 32 + lane)) * 9 + tap];  // OIHW
    unsigned m = __ballot_sync(0xffffffffu, v < 0.f);
    if (lane == 0) d_w3bits[g] = m;
}

__global__ void pack_w1_kernel(const float* __restrict__ w1) {
    int g = blockIdx.x * 8 + (threadIdx.x >> 5);   // oc2*8 + word
    int lane = threadIdx.x & 31;
    if (g >= C2 * 8) return;
    int word = g & 7;
    int oc   = g >> 3;
    float v = w1[(size_t)oc * CC + word * 32 + lane];
    unsigned m = __ballot_sync(0xffffffffu, v < 0.f);
    if (lane == 0) d_w1bits[g] = m;
}

// ================ fused megakernel, split-K layout ================
// block = b*28 + oh ; 512 threads.
// Phases 1-2: thread t -> (oc = t>>1, half = t&1); each handles 4 of 8 channel words.
// Phase 3:    thread t -> oc2 = t (one output channel each).
// Bit-words stored as ushort halves (warp = 16 ocs -> 1 ushort), read back as uint4.
__global__ __launch_bounds__(512, 2) void fused_kernel(
    const float* __restrict__ x,
    const float* __restrict__ g3, const float* __restrict__ b3,
    const float* __restrict__ m3, const float* __restrict__ v3,
    const float* __restrict__ g1, const float* __restrict__ b1,
    const float* __restrict__ m1, const float* __restrict__ v1,
    float* __restrict__ out) {
    int oh = blockIdx.x % OH;
    int b  = blockIdx.x / OH;
    int tid  = threadIdx.x;
    int lane = tid & 31;
    int wid  = tid >> 5;          // 0..15 ; warp covers oc = wid*16 .. wid*16+15
    int oc   = tid >> 1;          // 0..255
    int half = tid & 1;           // which 128-channel half (4 words)

    __shared__ __align__(16) unsigned short xs2[3][WW][16];  // sign bits of 3 input rows
    __shared__ float hs[OW][CC];                             // pooled, then h
    __shared__ __align__(16) unsigned short hb2[OW][16];     // sign bits of h

    // ---- Phase 1: binarize + pool (each thread reads half a row: 28 floats) ----
    {
        float acc[14];
#pragma unroll
        for (int r = 0; r < 3; r++) {
            int ih = 2 * oh - 1 + r;
            if (ih >= 0) {                             // uniform across block
                const float4* xp = (const float4*)(x + ((size_t)(b * CC + oc) * HH + ih) * WW + half * 28);
                float4 v[7];
#pragma unroll
                for (int i = 0; i < 7; i++) v[i] = xp[i];
                const float* vf = (const float*)v;
                // even lanes (half=0) hold cols 0..27; odd lanes hold cols 28..55
#pragma unroll
                for (int col = 0; col < 28; col++) {
                    unsigned m = __ballot_sync(0xffffffffu, vf[col] < 0.f);
                    if (lane == 0)      xs2[r][col]     [wid] = (unsigned short)cmpr_even(m);
                    else if (lane == 1) xs2[r][col + 28][wid] = (unsigned short)cmpr_even(m >> 1);
                }
                if (r == 1) {
#pragma unroll
                    for (int i = 0; i < 14; i++) acc[i] = vf[2 * i] + vf[2 * i + 1];
                } else if (r == 2) {
#pragma unroll
                    for (int i = 0; i < 14; i++) acc[i] += vf[2 * i] + vf[2 * i + 1];
                }
            }
        }
#pragma unroll
        for (int i = 0; i < 14; i++) hs[half * 14 + i][oc] = 0.25f * acc[i];
    }

    // conv3 weights for (oc, half): 36 words in registers (loaded pre-sync to hide latency)
    unsigned wreg[36];
    {
        const uint4* wp = (const uint4*)(d_w3bits + (size_t)oc * 72 + half * 4);
#pragma unroll
        for (int t9 = 0; t9 < 9; t9++) {
            uint4 q = wp[t9 * 2];                       // stride per tap = 8 words = 2 uint4
            wreg[t9 * 4 + 0] = q.x; wreg[t9 * 4 + 1] = q.y;
            wreg[t9 * 4 + 2] = q.z; wreg[t9 * 4 + 3] = q.w;
        }
    }
    float inv  = g3[oc] * rsqrtf(v3[oc] + 1e-5f);
    float bias = b3[oc] - m3[oc] * inv;
    __syncthreads();

    // ---- Phase 2: conv3x3 popcount (half channels) + pair-combine + BN + pool add ----
    {
        int khmin = (oh == 0) ? 1 : 0;
        int nrows = 3 - khmin;
        const char* xbase = (const char*)xs2 + half * 16;

        for (int ow = 0; ow < OW; ow++) {
            int iw = 2 * ow - 1;
            int sA = 0, sB = 0;
#pragma unroll
            for (int kh = 0; kh < 3; kh++) {
                if (kh < khmin) continue;               // uniform
#pragma unroll
                for (int kw = 0; kw < 3; kw++) {
                    int col = iw + kw;
                    if (col < 0) continue;              // only kw==0 at ow==0
                    uint4 a = *(const uint4*)(xbase + (size_t)(kh * WW + col) * 32);
                    const unsigned* w = &wreg[(kh * 3 + kw) * 4];
                    sA += __popc(a.x ^ w[0]) + __popc(a.y ^ w[1]);
                    sB += __popc(a.z ^ w[2]) + __popc(a.w ^ w[3]);
                }
            }
            int s = sA + sB;
            s += __shfl_xor_sync(0xffffffffu, s, 1);    // combine the two halves
            int ncols = (ow == 0) ? 2 : 3;
            float dot = (float)(nrows * ncols * CC - 2 * s);
            float h = fmaf(dot, inv, bias) + hs[ow][oc];
            hs[ow][oc] = h;                              // both pair lanes write same value
            unsigned m = __ballot_sync(0xffffffffu, h < 0.f);  // bits duplicated per pair
            if (lane == 0) hb2[ow][wid] = (unsigned short)cmpr_even(m);
        }
    }

    // conv1 weights for oc2 = tid (loaded pre-sync)
    unsigned w1r[8];
    {
        const uint4* wp = (const uint4*)(d_w1bits + (size_t)tid * 8);
        uint4 t0 = wp[0], t1 = wp[1];
        w1r[0] = t0.x; w1r[1] = t0.y; w1r[2] = t0.z; w1r[3] = t0.w;
        w1r[4] = t1.x; w1r[5] = t1.y; w1r[6] = t1.z; w1r[7] = t1.w;
    }
    float inv1  = g1[tid] * rsqrtf(v1[tid] + 1e-5f);
    float bias1 = b1[tid] - m1[tid] * inv1;
    __syncthreads();

    // ---- Phase 3: conv1x1 popcount + BN + concat shortcut -> out (NCHW) ----
    {
        int hc = tid & (CC - 1);
        float* orow = out + (((size_t)(b * C2 + tid)) * OH + oh) * OW;
#pragma unroll
        for (int ow4 = 0; ow4 < OW; ow4 += 4) {
            float4 o;
            float* p = (float*)&o;
#pragma unroll
            for (int k = 0; k < 4; k++) {
                int ow = ow4 + k;
                const uint4* hp = (const uint4*)&hb2[ow][0];  // 16 ushorts = 2 uint4
                uint4 a0 = hp[0], a1 = hp[1];
                int s = __popc(a0.x ^ w1r[0]) + __popc(a0.y ^ w1r[1])
                      + __popc(a0.z ^ w1r[2]) + __popc(a0.w ^ w1r[3])
                      + __popc(a1.x ^ w1r[4]) + __popc(a1.y ^ w1r[5])
                      + __popc(a1.z ^ w1r[6]) + __popc(a1.w ^ w1r[7]);
                p[k] = fmaf((float)(CC - 2 * s), inv1, bias1) + hs[ow][hc];
            }
            *(float4*)(orow + ow4) = o;
        }
    }
}

extern "C" void kernel_launch(void* const* d_in, const int* in_sizes, int n_in,
                              void* d_out, int out_size) {
    const float* x  = (const float*)d_in[0];
    const float* w3 = (const float*)d_in[1];
    const float* g3 = (const float*)d_in[2];
    const float* b3 = (const float*)d_in[3];
    const float* m3 = (const float*)d_in[4];
    const float* v3 = (const float*)d_in[5];
    const float* w1 = (const float*)d_in[6];
    const float* g1 = (const float*)d_in[7];
    const float* b1 = (const float*)d_in[8];
    const float* m1 = (const float*)d_in[9];
    const float* v1 = (const float*)d_in[10];
    float* out = (float*)d_out;
    (void)in_sizes; (void)n_in; (void)out_size;

    pack_w3_kernel<<<(CC * 9 * 8 + 7) / 8, 256>>>(w3);   // warp per word
    pack_w1_kernel<<<(C2 * 8 + 7) / 8, 256>>>(w1);
    fused_kernel<<<BB * OH, 512>>>(x, g3, b3, m3, v3, g1, b1, m1, v1, out);
}

// round 5
// speedup vs baseline: 1.8009x; 1.0037x over previous
#include <cuda_runtime.h>
#include <cstdint>

#define BB 32
#define CC 256
#define HH 56
#define WW 56
#define OH 28
#define OW 28
#define C2 512

// ---- scratch (static device arrays; no allocation) ----
__device__ unsigned d_w3bits[CC * 9 * 8];          // [oc][tap][8 words]
__device__ unsigned d_w1bits[C2 * 8];              // [oc2][8 words]

// extract even bits of x into low 16 bits
__device__ __forceinline__ unsigned cmpr_even(unsigned x) {
    x &= 0x55555555u;
    x = (x | (x >> 1)) & 0x33333333u;
    x = (x | (x >> 2)) & 0x0F0F0F0Fu;
    x = (x | (x >> 4)) & 0x00FF00FFu;
    x = (x | (x >> 8)) & 0x0000FFFFu;
    return x;
}

// ---------------- pack weights: warp per output word, lane = channel ----------------
__global__ void pack_w3_kernel(const float* __restrict__ w3) {
    int g = blockIdx.x * 8 + (threadIdx.x >> 5);   // linear word id = oc*72 + tap*8 + word
    int lane = threadIdx.x & 31;
    if (g >= CC * 9 * 8) return;
    int word = g & 7;
    int tap  = (g >> 3) % 9;
    int oc   = g / 72;
    float v = w3[((size_t)(oc * CC + word * 32 + lane)) * 9 + tap];  // OIHW
    unsigned m = __ballot_sync(0xffffffffu, v < 0.f);
    if (lane == 0) d_w3bits[g] = m;
}

__global__ void pack_w1_kernel(const float* __restrict__ w1) {
    int g = blockIdx.x * 8 + (threadIdx.x >> 5);   // oc2*8 + word
    int lane = threadIdx.x & 31;
    if (g >= C2 * 8) return;
    int word = g & 7;
    int oc   = g >> 3;
    float v = w1[(size_t)oc * CC + word * 32 + lane];
    unsigned m = __ballot_sync(0xffffffffu, v < 0.f);
    if (lane == 0) d_w1bits[g] = m;
}

// ================ fused megakernel, split-K layout ================
// block = b*28 + oh ; 512 threads.
// Phases 1-2: thread t -> (oc = t>>1, half = t&1); each handles 4 of 8 channel words.
// Phase 3:    thread t -> oc2 = t (one output channel each).
// Bit-words stored as ushort halves (warp = 16 ocs -> 1 ushort), read back as uint4.
__global__ __launch_bounds__(512, 2) void fused_kernel(
    const float* __restrict__ x,
    const float* __restrict__ g3, const float* __restrict__ b3,
    const float* __restrict__ m3, const float* __restrict__ v3,
    const float* __restrict__ g1, const float* __restrict__ b1,
    const float* __restrict__ m1, const float* __restrict__ v1,
    float* __restrict__ out) {
    int oh = blockIdx.x % OH;
    int b  = blockIdx.x / OH;
    int tid  = threadIdx.x;
    int lane = tid & 31;
    int wid  = tid >> 5;          // 0..15 ; warp covers oc = wid*16 .. wid*16+15
    int oc   = tid >> 1;          // 0..255
    int half = tid & 1;           // which 128-channel half (4 words)

    __shared__ __align__(16) unsigned short xs2[3][WW][16];  // sign bits of 3 input rows
    __shared__ float hs[OW][CC];                             // pooled, then h
    __shared__ __align__(16) unsigned short hb2[OW][16];     // sign bits of h

    // ---- Phase 1: binarize + pool (each thread reads half a row: 28 floats) ----
    {
        float acc[14];
#pragma unroll
        for (int r = 0; r < 3; r++) {
            int ih = 2 * oh - 1 + r;
            if (ih >= 0) {                             // uniform across block
                const float4* xp = (const float4*)(x + ((size_t)(b * CC + oc) * HH + ih) * WW + half * 28);
                float4 v[7];
#pragma unroll
                for (int i = 0; i < 7; i++) v[i] = xp[i];
                const float* vf = (const float*)v;
                // even lanes (half=0) hold cols 0..27; odd lanes hold cols 28..55
#pragma unroll
                for (int col = 0; col < 28; col++) {
                    unsigned m = __ballot_sync(0xffffffffu, vf[col] < 0.f);
                    if (lane == 0)      xs2[r][col]     [wid] = (unsigned short)cmpr_even(m);
                    else if (lane == 1) xs2[r][col + 28][wid] = (unsigned short)cmpr_even(m >> 1);
                }
                if (r == 1) {
#pragma unroll
                    for (int i = 0; i < 14; i++) acc[i] = vf[2 * i] + vf[2 * i + 1];
                } else if (r == 2) {
#pragma unroll
                    for (int i = 0; i < 14; i++) acc[i] += vf[2 * i] + vf[2 * i + 1];
                }
            }
        }
#pragma unroll
        for (int i = 0; i < 14; i++) hs[half * 14 + i][oc] = 0.25f * acc[i];
    }

    // conv3 weights for (oc, half): 36 words in registers (loaded pre-sync to hide latency)
    unsigned wreg[36];
    {
        const uint4* wp = (const uint4*)(d_w3bits + (size_t)oc * 72 + half * 4);
#pragma unroll
        for (int t9 = 0; t9 < 9; t9++) {
            uint4 q = wp[t9 * 2];                       // stride per tap = 8 words = 2 uint4
            wreg[t9 * 4 + 0] = q.x; wreg[t9 * 4 + 1] = q.y;
            wreg[t9 * 4 + 2] = q.z; wreg[t9 * 4 + 3] = q.w;
        }
    }
    float inv  = g3[oc] * rsqrtf(v3[oc] + 1e-5f);
    float bias = b3[oc] - m3[oc] * inv;
    __syncthreads();

    // ---- Phase 2: conv3x3 popcount (half channels) + pair-combine + BN + pool add ----
    {
        int khmin = (oh == 0) ? 1 : 0;
        int nrows = 3 - khmin;
        const char* xbase = (const char*)xs2 + half * 16;

        for (int ow = 0; ow < OW; ow++) {
            int iw = 2 * ow - 1;
            int sA = 0, sB = 0;
#pragma unroll
            for (int kh = 0; kh < 3; kh++) {
                if (kh < khmin) continue;               // uniform
#pragma unroll
                for (int kw = 0; kw < 3; kw++) {
                    int col = iw + kw;
                    if (col < 0) continue;              // only kw==0 at ow==0
                    uint4 a = *(const uint4*)(xbase + (size_t)(kh * WW + col) * 32);
                    const unsigned* w = &wreg[(kh * 3 + kw) * 4];
                    sA += __popc(a.x ^ w[0]) + __popc(a.y ^ w[1]);
                    sB += __popc(a.z ^ w[2]) + __popc(a.w ^ w[3]);
                }
            }
            int s = sA + sB;
            s += __shfl_xor_sync(0xffffffffu, s, 1);    // combine the two halves
            int ncols = (ow == 0) ? 2 : 3;
            float dot = (float)(nrows * ncols * CC - 2 * s);
            float h = fmaf(dot, inv, bias) + hs[ow][oc];
            hs[ow][oc] = h;                              // both pair lanes write same value
            unsigned m = __ballot_sync(0xffffffffu, h < 0.f);  // bits duplicated per pair
            if (lane == 0) hb2[ow][wid] = (unsigned short)cmpr_even(m);
        }
    }

    // conv1 weights for oc2 = tid (loaded pre-sync)
    unsigned w1r[8];
    {
        const uint4* wp = (const uint4*)(d_w1bits + (size_t)tid * 8);
        uint4 t0 = wp[0], t1 = wp[1];
        w1r[0] = t0.x; w1r[1] = t0.y; w1r[2] = t0.z; w1r[3] = t0.w;
        w1r[4] = t1.x; w1r[5] = t1.y; w1r[6] = t1.z; w1r[7] = t1.w;
    }
    float inv1  = g1[tid] * rsqrtf(v1[tid] + 1e-5f);
    float bias1 = b1[tid] - m1[tid] * inv1;
    __syncthreads();

    // ---- Phase 3: conv1x1 popcount + BN + concat shortcut -> out (NCHW) ----
    {
        int hc = tid & (CC - 1);
        float* orow = out + (((size_t)(b * C2 + tid)) * OH + oh) * OW;
#pragma unroll
        for (int ow4 = 0; ow4 < OW; ow4 += 4) {
            float4 o;
            float* p = (float*)&o;
#pragma unroll
            for (int k = 0; k < 4; k++) {
                int ow = ow4 + k;
                const uint4* hp = (const uint4*)&hb2[ow][0];  // 16 ushorts = 2 uint4
                uint4 a0 = hp[0], a1 = hp[1];
                int s = __popc(a0.x ^ w1r[0]) + __popc(a0.y ^ w1r[1])
                      + __popc(a0.z ^ w1r[2]) + __popc(a0.w ^ w1r[3])
                      + __popc(a1.x ^ w1r[4]) + __popc(a1.y ^ w1r[5])
                      + __popc(a1.z ^ w1r[6]) + __popc(a1.w ^ w1r[7]);
                p[k] = fmaf((float)(CC - 2 * s), inv1, bias1) + hs[ow][hc];
            }
            *(float4*)(orow + ow4) = o;
        }
    }
}

extern "C" void kernel_launch(void* const* d_in, const int* in_sizes, int n_in,
                              void* d_out, int out_size) {
    const float* x  = (const float*)d_in[0];
    const float* w3 = (const float*)d_in[1];
    const float* g3 = (const float*)d_in[2];
    const float* b3 = (const float*)d_in[3];
    const float* m3 = (const float*)d_in[4];
    const float* v3 = (const float*)d_in[5];
    const float* w1 = (const float*)d_in[6];
    const float* g1 = (const float*)d_in[7];
    const float* b1 = (const float*)d_in[8];
    const float* m1 = (const float*)d_in[9];
    const float* v1 = (const float*)d_in[10];
    float* out = (float*)d_out;
    (void)in_sizes; (void)n_in; (void)out_size;

    pack_w3_kernel<<<(CC * 9 * 8 + 7) / 8, 256>>>(w3);   // warp per word
    pack_w1_kernel<<<(C2 * 8 + 7) / 8, 256>>>(w1);
    fused_kernel<<<BB * OH, 512>>>(x, g3, b3, m3, v3, g1, b1, m1, v1, out);
}